// round 12
// baseline (speedup 1.0000x reference)
#include <cuda_runtime.h>
#include <cuda_bf16.h>
#include <cuda_fp16.h>
#include <math.h>
#include <stdint.h>

// ---------------------------------------------------------------------------
// Constants: T=8192; D_IN=1152, 4D_IN=4608, D_E=256, C=4, K=2048, dpc=64,
// H=4096, 4H=16384.
// Output (fp32): x_vq [8192*4096] | idx [8192*4] | total, commitment, entropy
// ---------------------------------------------------------------------------
#define T_TOKENS 8192
#define D_IN     1152
#define D_H1     4608
#define D_E      256
#define NC       4
#define NK       2048
#define DPC      64
#define D_H3     16384
#define D_OUT    4096

#define XVQ_ELEMS   (T_TOKENS * D_OUT)
#define IDX_ELEMS   (T_TOKENS * NC)

// Scratch (device globals)
__device__ __half g_x_hi [(size_t)T_TOKENS * D_IN];
__device__ __half g_x_lo [(size_t)T_TOKENS * D_IN];
__device__ __half g_w1_hi[(size_t)D_IN * D_H1];
__device__ __half g_w1_lo[(size_t)D_IN * D_H1];
__device__ __half g_w2_hi[(size_t)D_H1 * D_E];
__device__ __half g_w2_lo[(size_t)D_H1 * D_E];
__device__ __half g_h1_hi[(size_t)T_TOKENS * D_H1];
__device__ __half g_h1_lo[(size_t)T_TOKENS * D_H1];
__device__ float  g_z    [(size_t)T_TOKENS * D_E];
__device__ __half g_zq_h [(size_t)T_TOKENS * D_E];
__device__ __half g_w3_h [(size_t)D_E * D_H3];
__device__ __half g_h3_h [(size_t)T_TOKENS * D_H3];
__device__ __half g_w4_h [(size_t)D_H3 * D_OUT];
__device__ float g_esq[NC * NK];
__device__ int   g_counts[NC * NK];
__device__ float g_part[256];

__device__ __forceinline__ float gelu_exact(float x) {
    return 0.5f * x * (1.0f + erff(x * 0.70710678118654752440f));
}

// ---------------------------------------------------------------------------
// fp32 -> (fp16 hi, fp16 lo) split conversion
// ---------------------------------------------------------------------------
__global__ void f2h_split_kernel(const float* __restrict__ in,
                                 __half* __restrict__ hi,
                                 __half* __restrict__ lo, int n)
{
    int i = (blockIdx.x * blockDim.x + threadIdx.x) * 4;
    if (i >= n) return;
    float4 v = *(const float4*)(in + i);
    __half hx = __float2half_rn(v.x);
    __half hy = __float2half_rn(v.y);
    __half hz = __float2half_rn(v.z);
    __half hw = __float2half_rn(v.w);
    *(__half2*)(hi + i)     = __half2(hx, hy);
    *(__half2*)(hi + i + 2) = __half2(hz, hw);
    *(__half2*)(lo + i) = __half2(
        __float2half_rn(v.x - __half2float(hx)),
        __float2half_rn(v.y - __half2float(hy)));
    *(__half2*)(lo + i + 2) = __half2(
        __float2half_rn(v.z - __half2float(hz)),
        __float2half_rn(v.w - __half2float(hw)));
}

// ---------------------------------------------------------------------------
// fp32 -> fp16 conversion (W3, W4)
// ---------------------------------------------------------------------------
__global__ void f2h_kernel(const float* __restrict__ in,
                           __half* __restrict__ out, int n)
{
    int i = (blockIdx.x * blockDim.x + threadIdx.x) * 4;
    if (i >= n) return;
    float4 v = *(const float4*)(in + i);
    *(__half2*)(out + i)     = __floats2half2_rn(v.x, v.y);
    *(__half2*)(out + i + 2) = __floats2half2_rn(v.z, v.w);
}

// ---------------------------------------------------------------------------
// Common helpers
// ---------------------------------------------------------------------------
#define GBK 32
#define A_ST 40
#define B_ST 136
#define A_MAT (128 * A_ST)
#define B_MAT (GBK * B_ST)
#define SMEM_SPLIT_BYTES ((2 * 2 * A_MAT + 2 * 2 * B_MAT) * 2)
#define H16_STAGES 4
#define H16_SMEM_BYTES (H16_STAGES * (A_MAT + B_MAT) * 2)

__device__ __forceinline__ void ldsm_x4(uint32_t* r, uint32_t addr) {
    asm volatile("ldmatrix.sync.aligned.m8n8.x4.shared.b16 {%0,%1,%2,%3}, [%4];"
                 : "=r"(r[0]), "=r"(r[1]), "=r"(r[2]), "=r"(r[3]) : "r"(addr));
}
__device__ __forceinline__ void ldsm_x4_t(uint32_t* r, uint32_t addr) {
    asm volatile("ldmatrix.sync.aligned.m8n8.x4.trans.shared.b16 {%0,%1,%2,%3}, [%4];"
                 : "=r"(r[0]), "=r"(r[1]), "=r"(r[2]), "=r"(r[3]) : "r"(addr));
}
__device__ __forceinline__ void mma_f16(float* d, const uint32_t* a,
                                        uint32_t b0, uint32_t b1) {
    asm volatile(
        "mma.sync.aligned.m16n8k16.row.col.f32.f16.f16.f32 "
        "{%0,%1,%2,%3},{%4,%5,%6,%7},{%8,%9},{%0,%1,%2,%3};"
        : "+f"(d[0]), "+f"(d[1]), "+f"(d[2]), "+f"(d[3])
        : "r"(a[0]), "r"(a[1]), "r"(a[2]), "r"(a[3]), "r"(b0), "r"(b1));
}
__device__ __forceinline__ void cp16(uint32_t saddr, const void* g) {
    asm volatile("cp.async.cg.shared.global [%0], [%1], 16;"
                 :: "r"(saddr), "l"(g));
}

// ---------------------------------------------------------------------------
// 3-term split-fp16 GEMM (GEMM1/GEMM2): ~fp32 accuracy on tensor cores.
// (Proven R7 kernel, unchanged.)
// ---------------------------------------------------------------------------
__global__ void __launch_bounds__(256, 2)
splitf16_gemm_kernel(const __half* __restrict__ Ahi,
                     const __half* __restrict__ Alo,
                     const __half* __restrict__ Bhi,
                     const __half* __restrict__ Blo,
                     const float* __restrict__ bias,
                     float* __restrict__ outF,
                     __half* __restrict__ outHi,
                     __half* __restrict__ outLo,
                     int M, int N, int K, int mode)
{
    extern __shared__ __half smem[];
    __half* sA = smem;
    __half* sB = smem + 4 * A_MAT;

    const int tid  = threadIdx.x;
    const int lane = tid & 31;
    const int warp = tid >> 5;
    const int wm   = warp >> 1;
    const int wn   = warp & 1;
    const int bm   = blockIdx.y * 128;
    const int bn   = blockIdx.x * 128;

    const int arow = tid >> 2;
    const int acol = (tid & 3) * 8;
    const int brow = tid >> 4;
    const int bcol = (tid & 15) * 8;

    const __half* AgH = Ahi + (size_t)(bm + arow) * K + acol;
    const __half* AgL = Alo + (size_t)(bm + arow) * K + acol;
    const __half* BgH = Bhi + (size_t)brow * N + bn + bcol;
    const __half* BgL = Blo + (size_t)brow * N + bn + bcol;

    const uint32_t saBase = (uint32_t)__cvta_generic_to_shared(
        &sA[arow * A_ST + acol]);
    const uint32_t sbBase = (uint32_t)__cvta_generic_to_shared(
        &sB[brow * B_ST + bcol]);

    float acc[2][8][4];
#pragma unroll
    for (int i = 0; i < 2; i++)
#pragma unroll
        for (int j = 0; j < 8; j++)
#pragma unroll
            for (int l = 0; l < 4; l++) acc[i][j][l] = 0.0f;

    const int KT = K / GBK;

#define ISSUE_SPLIT(kt, buf)                                                  \
    do {                                                                      \
        const size_t ka = (size_t)(kt) * GBK;                                 \
        const size_t kb = (size_t)(kt) * GBK * N;                             \
        const uint32_t aOff = (buf) * (2 * A_MAT * 2);                        \
        const uint32_t bOff = (buf) * (2 * B_MAT * 2);                        \
        cp16(saBase + aOff, AgH + ka);                                        \
        cp16(saBase + aOff + 64 * A_ST * 2, AgH + ka + (size_t)64 * K);       \
        cp16(saBase + aOff + A_MAT * 2, AgL + ka);                            \
        cp16(saBase + aOff + A_MAT * 2 + 64 * A_ST * 2,                       \
             AgL + ka + (size_t)64 * K);                                      \
        cp16(sbBase + bOff, BgH + kb);                                        \
        cp16(sbBase + bOff + 16 * B_ST * 2, BgH + kb + (size_t)16 * N);       \
        cp16(sbBase + bOff + B_MAT * 2, BgL + kb);                            \
        cp16(sbBase + bOff + B_MAT * 2 + 16 * B_ST * 2,                       \
             BgL + kb + (size_t)16 * N);                                      \
        asm volatile("cp.async.commit_group;");                               \
    } while (0)

    ISSUE_SPLIT(0, 0);

    for (int kt = 0; kt < KT; kt++) {
        const int buf = kt & 1;
        if (kt + 1 < KT) {
            ISSUE_SPLIT(kt + 1, buf ^ 1);
            asm volatile("cp.async.wait_group 1;");
        } else {
            asm volatile("cp.async.wait_group 0;");
        }
        __syncthreads();

        const __half* cAhi = sA + buf * 2 * A_MAT;
        const __half* cAlo = cAhi + A_MAT;
        const __half* cBhi = sB + buf * 2 * B_MAT;
        const __half* cBlo = cBhi + B_MAT;

#pragma unroll
        for (int ks = 0; ks < 2; ks++) {
            uint32_t aH[2][4], aL[2][4];
#pragma unroll
            for (int mt = 0; mt < 2; mt++) {
                int row = wm * 32 + mt * 16 + (lane & 15);
                int col = ks * 16 + (lane >> 4) * 8;
                ldsm_x4(aH[mt], (uint32_t)__cvta_generic_to_shared(
                                    &cAhi[row * A_ST + col]));
                ldsm_x4(aL[mt], (uint32_t)__cvta_generic_to_shared(
                                    &cAlo[row * A_ST + col]));
            }
#pragma unroll
            for (int nt = 0; nt < 4; nt++) {
                int krow = ks * 16 + (lane & 15);
                int ncol = wn * 64 + nt * 16 + (lane >> 4) * 8;
                uint32_t bH[4], bL[4];
                ldsm_x4_t(bH, (uint32_t)__cvta_generic_to_shared(
                                  &cBhi[krow * B_ST + ncol]));
                ldsm_x4_t(bL, (uint32_t)__cvta_generic_to_shared(
                                  &cBlo[krow * B_ST + ncol]));
#pragma unroll
                for (int mt = 0; mt < 2; mt++) {
                    float* a0 = acc[mt][nt * 2 + 0];
                    float* a1 = acc[mt][nt * 2 + 1];
                    mma_f16(a0, aH[mt], bH[0], bH[1]);
                    mma_f16(a1, aH[mt], bH[2], bH[3]);
                    mma_f16(a0, aH[mt], bL[0], bL[1]);
                    mma_f16(a1, aH[mt], bL[2], bL[3]);
                    mma_f16(a0, aL[mt], bH[0], bH[1]);
                    mma_f16(a1, aL[mt], bH[2], bH[3]);
                }
            }
        }
        __syncthreads();
    }
#undef ISSUE_SPLIT

#pragma unroll
    for (int mt = 0; mt < 2; mt++) {
        const int r0 = bm + wm * 32 + mt * 16 + (lane >> 2);
#pragma unroll
        for (int nt8 = 0; nt8 < 8; nt8++) {
            const int col = bn + wn * 64 + nt8 * 8 + (lane & 3) * 2;
            const float bx = __ldg(&bias[col]);
            const float by = __ldg(&bias[col + 1]);
            float v0 = acc[mt][nt8][0] + bx;
            float v1 = acc[mt][nt8][1] + by;
            float v2 = acc[mt][nt8][2] + bx;
            float v3 = acc[mt][nt8][3] + by;
            if (mode == 1) {
                v0 = gelu_exact(v0); v1 = gelu_exact(v1);
                v2 = gelu_exact(v2); v3 = gelu_exact(v3);
                __half h0 = __float2half_rn(v0);
                __half h1 = __float2half_rn(v1);
                __half h2 = __float2half_rn(v2);
                __half h3v = __float2half_rn(v3);
                *(__half2*)(outHi + (size_t)r0 * N + col) = __half2(h0, h1);
                *(__half2*)(outHi + (size_t)(r0 + 8) * N + col) = __half2(h2, h3v);
                *(__half2*)(outLo + (size_t)r0 * N + col) = __half2(
                    __float2half_rn(v0 - __half2float(h0)),
                    __float2half_rn(v1 - __half2float(h1)));
                *(__half2*)(outLo + (size_t)(r0 + 8) * N + col) = __half2(
                    __float2half_rn(v2 - __half2float(h2)),
                    __float2half_rn(v3 - __half2float(h3v)));
            } else {
                *(float2*)(outF + (size_t)r0 * N + col)       = make_float2(v0, v1);
                *(float2*)(outF + (size_t)(r0 + 8) * N + col) = make_float2(v2, v3);
            }
        }
    }
}

// ---------------------------------------------------------------------------
// Plain fp16 GEMM (GEMM3/GEMM4), 128x128x32, 4-stage cp.async pipeline with
// a SINGLE barrier per iteration (4-stage reuse distance makes the
// post-compute barrier redundant: the cp.async issued at iteration kt
// overwrites stage (kt-1) mod 4, whose compute completed before this
// iteration's barrier). 75.8KB dynamic smem -> 2 CTAs/SM.
// mode 0: fp32 out + bias (GEMM4). mode 1: gelu -> fp16 out (GEMM3).
// ---------------------------------------------------------------------------
__global__ void __launch_bounds__(256, 2)
h16_gemm_kernel(const __half* __restrict__ A, const __half* __restrict__ B,
                const float* __restrict__ bias, float* __restrict__ outF,
                __half* __restrict__ outH, int M, int N, int K, int mode)
{
    extern __shared__ __half smem[];
    __half* sA = smem;                          // H16_STAGES x A_MAT
    __half* sB = smem + H16_STAGES * A_MAT;     // H16_STAGES x B_MAT

    const int tid  = threadIdx.x;
    const int lane = tid & 31;
    const int warp = tid >> 5;
    const int wm   = warp >> 1;
    const int wn   = warp & 1;
    const int bm   = blockIdx.y * 128;
    const int bn   = blockIdx.x * 128;

    const int arow = tid >> 2;
    const int acol = (tid & 3) * 8;
    const int brow = tid >> 4;
    const int bcol = (tid & 15) * 8;

    const __half* Ag = A + (size_t)(bm + arow) * K + acol;
    const __half* Bg = B + (size_t)brow * N + bn + bcol;

    const uint32_t saBase = (uint32_t)__cvta_generic_to_shared(
        &sA[arow * A_ST + acol]);
    const uint32_t sbBase = (uint32_t)__cvta_generic_to_shared(
        &sB[brow * B_ST + bcol]);

    float acc[2][8][4];
#pragma unroll
    for (int i = 0; i < 2; i++)
#pragma unroll
        for (int j = 0; j < 8; j++)
#pragma unroll
            for (int l = 0; l < 4; l++) acc[i][j][l] = 0.0f;

    const int KT = K / GBK;

#define ISSUE_H16(kt, buf)                                                   \
    do {                                                                     \
        const __half* ag = Ag + (size_t)(kt) * GBK;                          \
        const __half* bg = Bg + (size_t)(kt) * GBK * N;                      \
        const uint32_t aOff = (buf) * (A_MAT * 2);                           \
        const uint32_t bOff = (buf) * (B_MAT * 2);                           \
        cp16(saBase + aOff, ag);                                             \
        cp16(saBase + aOff + 64 * A_ST * 2, ag + (size_t)64 * K);            \
        cp16(sbBase + bOff, bg);                                             \
        cp16(sbBase + bOff + 16 * B_ST * 2, bg + (size_t)16 * N);            \
        asm volatile("cp.async.commit_group;");                              \
    } while (0)

    // Prologue: fill stages 0..2  (K here is always >= 3*GBK)
    ISSUE_H16(0, 0);
    ISSUE_H16(1, 1);
    ISSUE_H16(2, 2);

    int buf = 0;
    for (int kt = 0; kt < KT; kt++) {
        if (kt + 3 <= KT) {
            asm volatile("cp.async.wait_group 2;");
        } else if (kt + 2 == KT) {
            asm volatile("cp.async.wait_group 1;");
        } else {
            asm volatile("cp.async.wait_group 0;");
        }
        __syncthreads();

        // Overwrites stage (buf+3)&3 == stage of iteration kt-1 (safe: its
        // compute finished before the barrier above).
        if (kt + 3 < KT) {
            int nbuf = (buf + 3) & 3;
            ISSUE_H16(kt + 3, nbuf);
        }

        const __half* cA = sA + buf * A_MAT;
        const __half* cB = sB + buf * B_MAT;

#pragma unroll
        for (int ks = 0; ks < 2; ks++) {
            uint32_t afr[2][4];
#pragma unroll
            for (int mt = 0; mt < 2; mt++) {
                int row = wm * 32 + mt * 16 + (lane & 15);
                int col = ks * 16 + (lane >> 4) * 8;
                ldsm_x4(afr[mt], (uint32_t)__cvta_generic_to_shared(
                                     &cA[row * A_ST + col]));
            }
#pragma unroll
            for (int nt = 0; nt < 4; nt++) {
                int krow = ks * 16 + (lane & 15);
                int ncol = wn * 64 + nt * 16 + (lane >> 4) * 8;
                uint32_t bfr[4];
                ldsm_x4_t(bfr, (uint32_t)__cvta_generic_to_shared(
                                   &cB[krow * B_ST + ncol]));
#pragma unroll
                for (int mt = 0; mt < 2; mt++) {
                    mma_f16(acc[mt][nt * 2 + 0], afr[mt], bfr[0], bfr[1]);
                    mma_f16(acc[mt][nt * 2 + 1], afr[mt], bfr[2], bfr[3]);
                }
            }
        }

        buf = (buf + 1) & 3;
    }
#undef ISSUE_H16

    // All compute done; no trailing barrier needed before epilogue (each
    // thread reads only its own accumulators).
#pragma unroll
    for (int mt = 0; mt < 2; mt++) {
        const int r0 = bm + wm * 32 + mt * 16 + (lane >> 2);
#pragma unroll
        for (int nt8 = 0; nt8 < 8; nt8++) {
            const int col = bn + wn * 64 + nt8 * 8 + (lane & 3) * 2;
            const float bx = __ldg(&bias[col]);
            const float by = __ldg(&bias[col + 1]);
            float v0 = acc[mt][nt8][0] + bx;
            float v1 = acc[mt][nt8][1] + by;
            float v2 = acc[mt][nt8][2] + bx;
            float v3 = acc[mt][nt8][3] + by;
            if (mode == 1) {
                v0 = gelu_exact(v0); v1 = gelu_exact(v1);
                v2 = gelu_exact(v2); v3 = gelu_exact(v3);
                *(__half2*)(outH + (size_t)r0 * N + col) =
                    __floats2half2_rn(v0, v1);
                *(__half2*)(outH + (size_t)(r0 + 8) * N + col) =
                    __floats2half2_rn(v2, v3);
            } else {
                *(float2*)(outF + (size_t)r0 * N + col)       = make_float2(v0, v1);
                *(float2*)(outF + (size_t)(r0 + 8) * N + col) = make_float2(v2, v3);
            }
        }
    }
}

// ---------------------------------------------------------------------------
// e_sq, counts init
// ---------------------------------------------------------------------------
__global__ void esq_kernel(const float* __restrict__ cb, float* __restrict__ esq)
{
    int idx = blockIdx.x * blockDim.x + threadIdx.x;
    if (idx >= NC * NK) return;
    const float* e = cb + (size_t)idx * DPC;
    float s = 0.0f;
#pragma unroll
    for (int d = 0; d < DPC; d++) s += e[d] * e[d];
    esq[idx] = s;
}

__global__ void zero_counts_kernel(int* __restrict__ counts)
{
    int idx = blockIdx.x * blockDim.x + threadIdx.x;
    if (idx < NC * NK) counts[idx] = 0;
}

// ---------------------------------------------------------------------------
// VQ: fp32 argmin (exact), z_q emitted as fp16
// ---------------------------------------------------------------------------
#define VQ_TB 128
#define VQ_KC 128

__global__ void __launch_bounds__(VQ_TB)
vq_kernel(const float* __restrict__ z, const float* __restrict__ codebooks,
          const float* __restrict__ esq, __half* __restrict__ zqh,
          float* __restrict__ out_idx, float* __restrict__ partials,
          int* __restrict__ counts)
{
    __shared__ float E[VQ_KC][DPC];
    __shared__ float Esq_s[VQ_KC];
    __shared__ float red[VQ_TB];

    const int c   = blockIdx.y;
    const int tid = threadIdx.x;
    const int t   = blockIdx.x * VQ_TB + tid;

    float zr[DPC];
    {
        const float4* zp = (const float4*)(z + (size_t)t * D_E + c * DPC);
#pragma unroll
        for (int q = 0; q < DPC / 4; q++) {
            float4 v = zp[q];
            zr[4 * q + 0] = v.x; zr[4 * q + 1] = v.y;
            zr[4 * q + 2] = v.z; zr[4 * q + 3] = v.w;
        }
    }
    float zsq = 0.0f;
#pragma unroll
    for (int d = 0; d < DPC; d++) zsq = fmaf(zr[d], zr[d], zsq);

    const float* cb = codebooks + (size_t)c * NK * DPC;

    float best = 3.4e38f;
    int   bidx = 0;

    for (int k0 = 0; k0 < NK; k0 += VQ_KC) {
        for (int i = tid; i < VQ_KC * (DPC / 4); i += VQ_TB) {
            int row = i >> 4;
            int q   = i & 15;
            float4 v = *(const float4*)(cb + (size_t)(k0 + row) * DPC + q * 4);
            *(float4*)&E[row][q * 4] = v;
        }
        Esq_s[tid] = esq[c * NK + k0 + tid];
        __syncthreads();

        for (int j = 0; j < VQ_KC; j++) {
            float d0 = 0.f, d1 = 0.f, d2 = 0.f, d3 = 0.f;
#pragma unroll
            for (int d = 0; d < DPC; d += 4) {
                d0 = fmaf(zr[d + 0], E[j][d + 0], d0);
                d1 = fmaf(zr[d + 1], E[j][d + 1], d1);
                d2 = fmaf(zr[d + 2], E[j][d + 2], d2);
                d3 = fmaf(zr[d + 3], E[j][d + 3], d3);
            }
            float dot  = (d0 + d1) + (d2 + d3);
            float dist = zsq - 2.0f * dot + Esq_s[j];
            if (dist < best) { best = dist; bidx = k0 + j; }
        }
        __syncthreads();
    }

    const float* e = cb + (size_t)bidx * DPC;
    __half* zp = zqh + (size_t)t * D_E + c * DPC;
    float cs = 0.0f;
#pragma unroll
    for (int q = 0; q < DPC / 4; q++) {
        float4 ev = *(const float4*)(e + q * 4);
        *(__half2*)(zp + 4 * q)     = __floats2half2_rn(ev.x, ev.y);
        *(__half2*)(zp + 4 * q + 2) = __floats2half2_rn(ev.z, ev.w);
        float dx = zr[4 * q + 0] - ev.x;
        float dy = zr[4 * q + 1] - ev.y;
        float dz = zr[4 * q + 2] - ev.z;
        float dw = zr[4 * q + 3] - ev.w;
        cs += dx * dx + dy * dy + dz * dz + dw * dw;
    }

    atomicAdd(&counts[c * NK + bidx], 1);
    out_idx[(size_t)t * NC + c] = (float)bidx;

    red[tid] = cs;
    __syncthreads();
    for (int s = VQ_TB / 2; s > 0; s >>= 1) {
        if (tid < s) red[tid] += red[tid + s];
        __syncthreads();
    }
    if (tid == 0) partials[blockIdx.y * gridDim.x + blockIdx.x] = red[0];
}

// ---------------------------------------------------------------------------
// Finalize scalars
// ---------------------------------------------------------------------------
__global__ void __launch_bounds__(256)
finalize_kernel(const float* __restrict__ partials, int npart,
                const int* __restrict__ counts, float* __restrict__ out_scalars)
{
    __shared__ float sm[256];
    const int tid = threadIdx.x;

    float v = (tid < npart) ? partials[tid] : 0.0f;
    sm[tid] = v;
    __syncthreads();
    for (int s = 128; s > 0; s >>= 1) {
        if (tid < s) sm[tid] += sm[tid + s];
        __syncthreads();
    }
    if (tid == 0) {
        float commitment = 0.25f * sm[0] / (float)(T_TOKENS * D_E);
        out_scalars[0] = commitment;
        out_scalars[1] = commitment;
    }

    float ent_acc = 0.0f;
    for (int c = 0; c < NC; c++) {
        float s = 0.0f;
        for (int k = tid; k < NK; k += 256) {
            float p = (float)counts[c * NK + k] * (1.0f / 8192.0f);
            s -= p * logf(p + 1e-10f);
        }
        __syncthreads();
        sm[tid] = s;
        __syncthreads();
        for (int st = 128; st > 0; st >>= 1) {
            if (tid < st) sm[tid] += sm[tid + st];
            __syncthreads();
        }
        if (tid == 0) ent_acc += sm[0];
        __syncthreads();
    }
    if (tid == 0) out_scalars[2] = ent_acc * 0.25f;
}

// ---------------------------------------------------------------------------
// Host launcher. Inputs: x, W1, b1, W2, b2, codebooks, W3, b3, W4, b4
// ---------------------------------------------------------------------------
extern "C" void kernel_launch(void* const* d_in, const int* in_sizes, int n_in,
                              void* d_out, int out_size)
{
    const float* x   = (const float*)d_in[0];
    const float* W1  = (const float*)d_in[1];
    const float* b1  = (const float*)d_in[2];
    const float* W2  = (const float*)d_in[3];
    const float* b2  = (const float*)d_in[4];
    const float* cb  = (const float*)d_in[5];
    const float* W3  = (const float*)d_in[6];
    const float* b3  = (const float*)d_in[7];
    const float* W4  = (const float*)d_in[8];
    const float* b4  = (const float*)d_in[9];

    float* out = (float*)d_out;

    float *z, *esq, *part;
    __half *xH, *xL, *w1H, *w1L, *w2H, *w2L, *h1H, *h1L, *zqh, *w3h, *h3h, *w4h;
    int* counts;
    cudaGetSymbolAddress((void**)&xH,  g_x_hi);
    cudaGetSymbolAddress((void**)&xL,  g_x_lo);
    cudaGetSymbolAddress((void**)&w1H, g_w1_hi);
    cudaGetSymbolAddress((void**)&w1L, g_w1_lo);
    cudaGetSymbolAddress((void**)&w2H, g_w2_hi);
    cudaGetSymbolAddress((void**)&w2L, g_w2_lo);
    cudaGetSymbolAddress((void**)&h1H, g_h1_hi);
    cudaGetSymbolAddress((void**)&h1L, g_h1_lo);
    cudaGetSymbolAddress((void**)&z,   g_z);
    cudaGetSymbolAddress((void**)&zqh, g_zq_h);
    cudaGetSymbolAddress((void**)&w3h, g_w3_h);
    cudaGetSymbolAddress((void**)&h3h, g_h3_h);
    cudaGetSymbolAddress((void**)&w4h, g_w4_h);
    cudaGetSymbolAddress((void**)&esq, g_esq);
    cudaGetSymbolAddress((void**)&part, g_part);
    cudaGetSymbolAddress((void**)&counts, g_counts);

    cudaFuncSetAttribute(splitf16_gemm_kernel,
                         cudaFuncAttributeMaxDynamicSharedMemorySize,
                         SMEM_SPLIT_BYTES);
    cudaFuncSetAttribute(h16_gemm_kernel,
                         cudaFuncAttributeMaxDynamicSharedMemorySize,
                         H16_SMEM_BYTES);

    // 0) conversions
    {
        int nx = T_TOKENS * D_IN;
        int n1 = D_IN * D_H1;
        int n2 = D_H1 * D_E;
        int n3 = D_E * D_H3;
        int n4 = D_H3 * D_OUT;
        f2h_split_kernel<<<(nx / 4 + 255) / 256, 256>>>(x, xH, xL, nx);
        f2h_split_kernel<<<(n1 / 4 + 255) / 256, 256>>>(W1, w1H, w1L, n1);
        f2h_split_kernel<<<(n2 / 4 + 255) / 256, 256>>>(W2, w2H, w2L, n2);
        f2h_kernel<<<(n3 / 4 + 255) / 256, 256>>>(W3, w3h, n3);
        f2h_kernel<<<(n4 / 4 + 255) / 256, 256>>>(W4, w4h, n4);
    }

    // 1) h1 = gelu(x @ W1 + b1)   split-fp16 3-term -> split-fp16 h1
    splitf16_gemm_kernel<<<dim3(D_H1 / 128, T_TOKENS / 128), 256,
                           SMEM_SPLIT_BYTES>>>(
        xH, xL, w1H, w1L, b1, nullptr, h1H, h1L,
        T_TOKENS, D_H1, D_IN, 1);

    // 2) z = h1 @ W2 + b2         split-fp16 3-term -> fp32 z
    splitf16_gemm_kernel<<<dim3(D_E / 128, T_TOKENS / 128), 256,
                           SMEM_SPLIT_BYTES>>>(
        h1H, h1L, w2H, w2L, b2, z, nullptr, nullptr,
        T_TOKENS, D_E, D_H1, 0);

    // 3) code norms + zero counts
    esq_kernel<<<(NC * NK + 255) / 256, 256>>>(cb, esq);
    zero_counts_kernel<<<(NC * NK + 255) / 256, 256>>>(counts);

    // 4) VQ (fp32 argmin, fp16 z_q)
    vq_kernel<<<dim3(T_TOKENS / VQ_TB, NC), VQ_TB>>>(
        z, cb, esq, zqh, out + XVQ_ELEMS, part, counts);

    // 5) scalars
    finalize_kernel<<<1, 256>>>(part, (T_TOKENS / VQ_TB) * NC, counts,
                                out + XVQ_ELEMS + IDX_ELEMS);

    // 6) h3 = gelu(zq @ W3 + b3)  fp16 4-stage single-barrier pipeline
    h16_gemm_kernel<<<dim3(D_H3 / 128, T_TOKENS / 128), 256, H16_SMEM_BYTES>>>(
        zqh, w3h, b3, nullptr, h3h, T_TOKENS, D_H3, D_E, 1);

    // 7) x_vq = h3 @ W4 + b4 -> out  fp16 4-stage single-barrier pipeline
    h16_gemm_kernel<<<dim3(D_OUT / 128, T_TOKENS / 128), 256, H16_SMEM_BYTES>>>(
        h3h, w4h, b4, out, nullptr, T_TOKENS, D_OUT, D_H3, 0);
}

// round 13
// speedup vs baseline: 1.0078x; 1.0078x over previous
#include <cuda_runtime.h>
#include <cuda_bf16.h>
#include <cuda_fp16.h>
#include <math.h>
#include <stdint.h>

// ---------------------------------------------------------------------------
// Constants: T=8192; D_IN=1152, 4D_IN=4608, D_E=256, C=4, K=2048, dpc=64,
// H=4096, 4H=16384.
// Output (fp32): x_vq [8192*4096] | idx [8192*4] | total, commitment, entropy
// ---------------------------------------------------------------------------
#define T_TOKENS 8192
#define D_IN     1152
#define D_H1     4608
#define D_E      256
#define NC       4
#define NK       2048
#define DPC      64
#define D_H3     16384
#define D_OUT    4096

#define XVQ_ELEMS   (T_TOKENS * D_OUT)
#define IDX_ELEMS   (T_TOKENS * NC)

// Scratch (device globals)
__device__ __half g_x_hi [(size_t)T_TOKENS * D_IN];
__device__ __half g_x_lo [(size_t)T_TOKENS * D_IN];
__device__ __half g_w1_hi[(size_t)D_IN * D_H1];
__device__ __half g_w1_lo[(size_t)D_IN * D_H1];
__device__ __half g_w2_hi[(size_t)D_H1 * D_E];
__device__ __half g_w2_lo[(size_t)D_H1 * D_E];
__device__ __half g_h1_hi[(size_t)T_TOKENS * D_H1];
__device__ __half g_h1_lo[(size_t)T_TOKENS * D_H1];
__device__ float  g_z    [(size_t)T_TOKENS * D_E];
__device__ __half g_zq_h [(size_t)T_TOKENS * D_E];
__device__ __half g_w3_h [(size_t)D_E * D_H3];
__device__ __half g_h3_h [(size_t)T_TOKENS * D_H3];
__device__ __half g_w4_h [(size_t)D_H3 * D_OUT];
__device__ float g_esq[NC * NK];
__device__ int   g_counts[NC * NK];
__device__ float g_part[256];

__device__ __forceinline__ float gelu_exact(float x) {
    return 0.5f * x * (1.0f + erff(x * 0.70710678118654752440f));
}

// ---------------------------------------------------------------------------
// fp32 -> (fp16 hi, fp16 lo) split conversion
// ---------------------------------------------------------------------------
__global__ void f2h_split_kernel(const float* __restrict__ in,
                                 __half* __restrict__ hi,
                                 __half* __restrict__ lo, int n)
{
    int i = (blockIdx.x * blockDim.x + threadIdx.x) * 4;
    if (i >= n) return;
    float4 v = *(const float4*)(in + i);
    __half hx = __float2half_rn(v.x);
    __half hy = __float2half_rn(v.y);
    __half hz = __float2half_rn(v.z);
    __half hw = __float2half_rn(v.w);
    *(__half2*)(hi + i)     = __half2(hx, hy);
    *(__half2*)(hi + i + 2) = __half2(hz, hw);
    *(__half2*)(lo + i) = __half2(
        __float2half_rn(v.x - __half2float(hx)),
        __float2half_rn(v.y - __half2float(hy)));
    *(__half2*)(lo + i + 2) = __half2(
        __float2half_rn(v.z - __half2float(hz)),
        __float2half_rn(v.w - __half2float(hw)));
}

// ---------------------------------------------------------------------------
// fp32 -> fp16 conversion (W3, W4)
// ---------------------------------------------------------------------------
__global__ void f2h_kernel(const float* __restrict__ in,
                           __half* __restrict__ out, int n)
{
    int i = (blockIdx.x * blockDim.x + threadIdx.x) * 4;
    if (i >= n) return;
    float4 v = *(const float4*)(in + i);
    *(__half2*)(out + i)     = __floats2half2_rn(v.x, v.y);
    *(__half2*)(out + i + 2) = __floats2half2_rn(v.z, v.w);
}

// ---------------------------------------------------------------------------
// Common helpers
// ---------------------------------------------------------------------------
#define GBK 32
#define A_ST 40
#define B_ST 136
#define A_MAT (128 * A_ST)
#define B_MAT (GBK * B_ST)
#define SMEM_SPLIT_BYTES ((2 * 2 * A_MAT + 2 * 2 * B_MAT) * 2)
#define H16_STAGES 4
#define H16_SMEM_BYTES (H16_STAGES * (A_MAT + B_MAT) * 2)

__device__ __forceinline__ void ldsm_x4(uint32_t* r, uint32_t addr) {
    asm volatile("ldmatrix.sync.aligned.m8n8.x4.shared.b16 {%0,%1,%2,%3}, [%4];"
                 : "=r"(r[0]), "=r"(r[1]), "=r"(r[2]), "=r"(r[3]) : "r"(addr));
}
__device__ __forceinline__ void ldsm_x4_t(uint32_t* r, uint32_t addr) {
    asm volatile("ldmatrix.sync.aligned.m8n8.x4.trans.shared.b16 {%0,%1,%2,%3}, [%4];"
                 : "=r"(r[0]), "=r"(r[1]), "=r"(r[2]), "=r"(r[3]) : "r"(addr));
}
__device__ __forceinline__ void mma_f16(float* d, const uint32_t* a,
                                        uint32_t b0, uint32_t b1) {
    asm volatile(
        "mma.sync.aligned.m16n8k16.row.col.f32.f16.f16.f32 "
        "{%0,%1,%2,%3},{%4,%5,%6,%7},{%8,%9},{%0,%1,%2,%3};"
        : "+f"(d[0]), "+f"(d[1]), "+f"(d[2]), "+f"(d[3])
        : "r"(a[0]), "r"(a[1]), "r"(a[2]), "r"(a[3]), "r"(b0), "r"(b1));
}
__device__ __forceinline__ void cp16(uint32_t saddr, const void* g) {
    asm volatile("cp.async.cg.shared.global [%0], [%1], 16;"
                 :: "r"(saddr), "l"(g));
}

// ---------------------------------------------------------------------------
// 3-term split-fp16 GEMM (GEMM1/GEMM2): ~fp32 accuracy on tensor cores.
// (Proven R7 kernel, unchanged.)
// ---------------------------------------------------------------------------
__global__ void __launch_bounds__(256, 2)
splitf16_gemm_kernel(const __half* __restrict__ Ahi,
                     const __half* __restrict__ Alo,
                     const __half* __restrict__ Bhi,
                     const __half* __restrict__ Blo,
                     const float* __restrict__ bias,
                     float* __restrict__ outF,
                     __half* __restrict__ outHi,
                     __half* __restrict__ outLo,
                     int M, int N, int K, int mode)
{
    extern __shared__ __half smem[];
    __half* sA = smem;
    __half* sB = smem + 4 * A_MAT;

    const int tid  = threadIdx.x;
    const int lane = tid & 31;
    const int warp = tid >> 5;
    const int wm   = warp >> 1;
    const int wn   = warp & 1;
    const int bm   = blockIdx.y * 128;
    const int bn   = blockIdx.x * 128;

    const int arow = tid >> 2;
    const int acol = (tid & 3) * 8;
    const int brow = tid >> 4;
    const int bcol = (tid & 15) * 8;

    const __half* AgH = Ahi + (size_t)(bm + arow) * K + acol;
    const __half* AgL = Alo + (size_t)(bm + arow) * K + acol;
    const __half* BgH = Bhi + (size_t)brow * N + bn + bcol;
    const __half* BgL = Blo + (size_t)brow * N + bn + bcol;

    const uint32_t saBase = (uint32_t)__cvta_generic_to_shared(
        &sA[arow * A_ST + acol]);
    const uint32_t sbBase = (uint32_t)__cvta_generic_to_shared(
        &sB[brow * B_ST + bcol]);

    float acc[2][8][4];
#pragma unroll
    for (int i = 0; i < 2; i++)
#pragma unroll
        for (int j = 0; j < 8; j++)
#pragma unroll
            for (int l = 0; l < 4; l++) acc[i][j][l] = 0.0f;

    const int KT = K / GBK;

#define ISSUE_SPLIT(kt, buf)                                                  \
    do {                                                                      \
        const size_t ka = (size_t)(kt) * GBK;                                 \
        const size_t kb = (size_t)(kt) * GBK * N;                             \
        const uint32_t aOff = (buf) * (2 * A_MAT * 2);                        \
        const uint32_t bOff = (buf) * (2 * B_MAT * 2);                        \
        cp16(saBase + aOff, AgH + ka);                                        \
        cp16(saBase + aOff + 64 * A_ST * 2, AgH + ka + (size_t)64 * K);       \
        cp16(saBase + aOff + A_MAT * 2, AgL + ka);                            \
        cp16(saBase + aOff + A_MAT * 2 + 64 * A_ST * 2,                       \
             AgL + ka + (size_t)64 * K);                                      \
        cp16(sbBase + bOff, BgH + kb);                                        \
        cp16(sbBase + bOff + 16 * B_ST * 2, BgH + kb + (size_t)16 * N);       \
        cp16(sbBase + bOff + B_MAT * 2, BgL + kb);                            \
        cp16(sbBase + bOff + B_MAT * 2 + 16 * B_ST * 2,                       \
             BgL + kb + (size_t)16 * N);                                      \
        asm volatile("cp.async.commit_group;");                               \
    } while (0)

    ISSUE_SPLIT(0, 0);

    for (int kt = 0; kt < KT; kt++) {
        const int buf = kt & 1;
        if (kt + 1 < KT) {
            ISSUE_SPLIT(kt + 1, buf ^ 1);
            asm volatile("cp.async.wait_group 1;");
        } else {
            asm volatile("cp.async.wait_group 0;");
        }
        __syncthreads();

        const __half* cAhi = sA + buf * 2 * A_MAT;
        const __half* cAlo = cAhi + A_MAT;
        const __half* cBhi = sB + buf * 2 * B_MAT;
        const __half* cBlo = cBhi + B_MAT;

#pragma unroll
        for (int ks = 0; ks < 2; ks++) {
            uint32_t aH[2][4], aL[2][4];
#pragma unroll
            for (int mt = 0; mt < 2; mt++) {
                int row = wm * 32 + mt * 16 + (lane & 15);
                int col = ks * 16 + (lane >> 4) * 8;
                ldsm_x4(aH[mt], (uint32_t)__cvta_generic_to_shared(
                                    &cAhi[row * A_ST + col]));
                ldsm_x4(aL[mt], (uint32_t)__cvta_generic_to_shared(
                                    &cAlo[row * A_ST + col]));
            }
#pragma unroll
            for (int nt = 0; nt < 4; nt++) {
                int krow = ks * 16 + (lane & 15);
                int ncol = wn * 64 + nt * 16 + (lane >> 4) * 8;
                uint32_t bH[4], bL[4];
                ldsm_x4_t(bH, (uint32_t)__cvta_generic_to_shared(
                                  &cBhi[krow * B_ST + ncol]));
                ldsm_x4_t(bL, (uint32_t)__cvta_generic_to_shared(
                                  &cBlo[krow * B_ST + ncol]));
#pragma unroll
                for (int mt = 0; mt < 2; mt++) {
                    float* a0 = acc[mt][nt * 2 + 0];
                    float* a1 = acc[mt][nt * 2 + 1];
                    mma_f16(a0, aH[mt], bH[0], bH[1]);
                    mma_f16(a1, aH[mt], bH[2], bH[3]);
                    mma_f16(a0, aH[mt], bL[0], bL[1]);
                    mma_f16(a1, aH[mt], bL[2], bL[3]);
                    mma_f16(a0, aL[mt], bH[0], bH[1]);
                    mma_f16(a1, aL[mt], bH[2], bH[3]);
                }
            }
        }
        __syncthreads();
    }
#undef ISSUE_SPLIT

#pragma unroll
    for (int mt = 0; mt < 2; mt++) {
        const int r0 = bm + wm * 32 + mt * 16 + (lane >> 2);
#pragma unroll
        for (int nt8 = 0; nt8 < 8; nt8++) {
            const int col = bn + wn * 64 + nt8 * 8 + (lane & 3) * 2;
            const float bx = __ldg(&bias[col]);
            const float by = __ldg(&bias[col + 1]);
            float v0 = acc[mt][nt8][0] + bx;
            float v1 = acc[mt][nt8][1] + by;
            float v2 = acc[mt][nt8][2] + bx;
            float v3 = acc[mt][nt8][3] + by;
            if (mode == 1) {
                v0 = gelu_exact(v0); v1 = gelu_exact(v1);
                v2 = gelu_exact(v2); v3 = gelu_exact(v3);
                __half h0 = __float2half_rn(v0);
                __half h1 = __float2half_rn(v1);
                __half h2 = __float2half_rn(v2);
                __half h3v = __float2half_rn(v3);
                *(__half2*)(outHi + (size_t)r0 * N + col) = __half2(h0, h1);
                *(__half2*)(outHi + (size_t)(r0 + 8) * N + col) = __half2(h2, h3v);
                *(__half2*)(outLo + (size_t)r0 * N + col) = __half2(
                    __float2half_rn(v0 - __half2float(h0)),
                    __float2half_rn(v1 - __half2float(h1)));
                *(__half2*)(outLo + (size_t)(r0 + 8) * N + col) = __half2(
                    __float2half_rn(v2 - __half2float(h2)),
                    __float2half_rn(v3 - __half2float(h3v)));
            } else {
                *(float2*)(outF + (size_t)r0 * N + col)       = make_float2(v0, v1);
                *(float2*)(outF + (size_t)(r0 + 8) * N + col) = make_float2(v2, v3);
            }
        }
    }
}

// ---------------------------------------------------------------------------
// Plain fp16 GEMM (GEMM3/GEMM4), 128x128x32, 4-stage cp.async pipeline with
// a SINGLE barrier per iteration (4-stage reuse distance makes the
// post-compute barrier redundant: the cp.async issued at iteration kt
// overwrites stage (kt-1) mod 4, whose compute completed before this
// iteration's barrier). 75.8KB dynamic smem -> 2 CTAs/SM.
// mode 0: fp32 out + bias (GEMM4). mode 1: gelu -> fp16 out (GEMM3).
// ---------------------------------------------------------------------------
__global__ void __launch_bounds__(256, 2)
h16_gemm_kernel(const __half* __restrict__ A, const __half* __restrict__ B,
                const float* __restrict__ bias, float* __restrict__ outF,
                __half* __restrict__ outH, int M, int N, int K, int mode)
{
    extern __shared__ __half smem[];
    __half* sA = smem;                          // H16_STAGES x A_MAT
    __half* sB = smem + H16_STAGES * A_MAT;     // H16_STAGES x B_MAT

    const int tid  = threadIdx.x;
    const int lane = tid & 31;
    const int warp = tid >> 5;
    const int wm   = warp >> 1;
    const int wn   = warp & 1;
    const int bm   = blockIdx.y * 128;
    const int bn   = blockIdx.x * 128;

    const int arow = tid >> 2;
    const int acol = (tid & 3) * 8;
    const int brow = tid >> 4;
    const int bcol = (tid & 15) * 8;

    const __half* Ag = A + (size_t)(bm + arow) * K + acol;
    const __half* Bg = B + (size_t)brow * N + bn + bcol;

    const uint32_t saBase = (uint32_t)__cvta_generic_to_shared(
        &sA[arow * A_ST + acol]);
    const uint32_t sbBase = (uint32_t)__cvta_generic_to_shared(
        &sB[brow * B_ST + bcol]);

    float acc[2][8][4];
#pragma unroll
    for (int i = 0; i < 2; i++)
#pragma unroll
        for (int j = 0; j < 8; j++)
#pragma unroll
            for (int l = 0; l < 4; l++) acc[i][j][l] = 0.0f;

    const int KT = K / GBK;

#define ISSUE_H16(kt, buf)                                                   \
    do {                                                                     \
        const __half* ag = Ag + (size_t)(kt) * GBK;                          \
        const __half* bg = Bg + (size_t)(kt) * GBK * N;                      \
        const uint32_t aOff = (buf) * (A_MAT * 2);                           \
        const uint32_t bOff = (buf) * (B_MAT * 2);                           \
        cp16(saBase + aOff, ag);                                             \
        cp16(saBase + aOff + 64 * A_ST * 2, ag + (size_t)64 * K);            \
        cp16(sbBase + bOff, bg);                                             \
        cp16(sbBase + bOff + 16 * B_ST * 2, bg + (size_t)16 * N);            \
        asm volatile("cp.async.commit_group;");                              \
    } while (0)

    // Prologue: fill stages 0..2  (K here is always >= 3*GBK)
    ISSUE_H16(0, 0);
    ISSUE_H16(1, 1);
    ISSUE_H16(2, 2);

    int buf = 0;
    for (int kt = 0; kt < KT; kt++) {
        if (kt + 3 <= KT) {
            asm volatile("cp.async.wait_group 2;");
        } else if (kt + 2 == KT) {
            asm volatile("cp.async.wait_group 1;");
        } else {
            asm volatile("cp.async.wait_group 0;");
        }
        __syncthreads();

        // Overwrites stage (buf+3)&3 == stage of iteration kt-1 (safe: its
        // compute finished before the barrier above).
        if (kt + 3 < KT) {
            int nbuf = (buf + 3) & 3;
            ISSUE_H16(kt + 3, nbuf);
        }

        const __half* cA = sA + buf * A_MAT;
        const __half* cB = sB + buf * B_MAT;

#pragma unroll
        for (int ks = 0; ks < 2; ks++) {
            uint32_t afr[2][4];
#pragma unroll
            for (int mt = 0; mt < 2; mt++) {
                int row = wm * 32 + mt * 16 + (lane & 15);
                int col = ks * 16 + (lane >> 4) * 8;
                ldsm_x4(afr[mt], (uint32_t)__cvta_generic_to_shared(
                                     &cA[row * A_ST + col]));
            }
#pragma unroll
            for (int nt = 0; nt < 4; nt++) {
                int krow = ks * 16 + (lane & 15);
                int ncol = wn * 64 + nt * 16 + (lane >> 4) * 8;
                uint32_t bfr[4];
                ldsm_x4_t(bfr, (uint32_t)__cvta_generic_to_shared(
                                   &cB[krow * B_ST + ncol]));
#pragma unroll
                for (int mt = 0; mt < 2; mt++) {
                    mma_f16(acc[mt][nt * 2 + 0], afr[mt], bfr[0], bfr[1]);
                    mma_f16(acc[mt][nt * 2 + 1], afr[mt], bfr[2], bfr[3]);
                }
            }
        }

        buf = (buf + 1) & 3;
    }
#undef ISSUE_H16

    // All compute done; no trailing barrier needed before epilogue (each
    // thread reads only its own accumulators).
#pragma unroll
    for (int mt = 0; mt < 2; mt++) {
        const int r0 = bm + wm * 32 + mt * 16 + (lane >> 2);
#pragma unroll
        for (int nt8 = 0; nt8 < 8; nt8++) {
            const int col = bn + wn * 64 + nt8 * 8 + (lane & 3) * 2;
            const float bx = __ldg(&bias[col]);
            const float by = __ldg(&bias[col + 1]);
            float v0 = acc[mt][nt8][0] + bx;
            float v1 = acc[mt][nt8][1] + by;
            float v2 = acc[mt][nt8][2] + bx;
            float v3 = acc[mt][nt8][3] + by;
            if (mode == 1) {
                v0 = gelu_exact(v0); v1 = gelu_exact(v1);
                v2 = gelu_exact(v2); v3 = gelu_exact(v3);
                *(__half2*)(outH + (size_t)r0 * N + col) =
                    __floats2half2_rn(v0, v1);
                *(__half2*)(outH + (size_t)(r0 + 8) * N + col) =
                    __floats2half2_rn(v2, v3);
            } else {
                *(float2*)(outF + (size_t)r0 * N + col)       = make_float2(v0, v1);
                *(float2*)(outF + (size_t)(r0 + 8) * N + col) = make_float2(v2, v3);
            }
        }
    }
}

// ---------------------------------------------------------------------------
// e_sq, counts init
// ---------------------------------------------------------------------------
__global__ void esq_kernel(const float* __restrict__ cb, float* __restrict__ esq)
{
    int idx = blockIdx.x * blockDim.x + threadIdx.x;
    if (idx >= NC * NK) return;
    const float* e = cb + (size_t)idx * DPC;
    float s = 0.0f;
#pragma unroll
    for (int d = 0; d < DPC; d++) s += e[d] * e[d];
    esq[idx] = s;
}

__global__ void zero_counts_kernel(int* __restrict__ counts)
{
    int idx = blockIdx.x * blockDim.x + threadIdx.x;
    if (idx < NC * NK) counts[idx] = 0;
}

// ---------------------------------------------------------------------------
// VQ: fp32 argmin (exact), z_q emitted as fp16
// ---------------------------------------------------------------------------
#define VQ_TB 128
#define VQ_KC 128

__global__ void __launch_bounds__(VQ_TB)
vq_kernel(const float* __restrict__ z, const float* __restrict__ codebooks,
          const float* __restrict__ esq, __half* __restrict__ zqh,
          float* __restrict__ out_idx, float* __restrict__ partials,
          int* __restrict__ counts)
{
    __shared__ float E[VQ_KC][DPC];
    __shared__ float Esq_s[VQ_KC];
    __shared__ float red[VQ_TB];

    const int c   = blockIdx.y;
    const int tid = threadIdx.x;
    const int t   = blockIdx.x * VQ_TB + tid;

    float zr[DPC];
    {
        const float4* zp = (const float4*)(z + (size_t)t * D_E + c * DPC);
#pragma unroll
        for (int q = 0; q < DPC / 4; q++) {
            float4 v = zp[q];
            zr[4 * q + 0] = v.x; zr[4 * q + 1] = v.y;
            zr[4 * q + 2] = v.z; zr[4 * q + 3] = v.w;
        }
    }
    float zsq = 0.0f;
#pragma unroll
    for (int d = 0; d < DPC; d++) zsq = fmaf(zr[d], zr[d], zsq);

    const float* cb = codebooks + (size_t)c * NK * DPC;

    float best = 3.4e38f;
    int   bidx = 0;

    for (int k0 = 0; k0 < NK; k0 += VQ_KC) {
        for (int i = tid; i < VQ_KC * (DPC / 4); i += VQ_TB) {
            int row = i >> 4;
            int q   = i & 15;
            float4 v = *(const float4*)(cb + (size_t)(k0 + row) * DPC + q * 4);
            *(float4*)&E[row][q * 4] = v;
        }
        Esq_s[tid] = esq[c * NK + k0 + tid];
        __syncthreads();

        for (int j = 0; j < VQ_KC; j++) {
            float d0 = 0.f, d1 = 0.f, d2 = 0.f, d3 = 0.f;
#pragma unroll
            for (int d = 0; d < DPC; d += 4) {
                d0 = fmaf(zr[d + 0], E[j][d + 0], d0);
                d1 = fmaf(zr[d + 1], E[j][d + 1], d1);
                d2 = fmaf(zr[d + 2], E[j][d + 2], d2);
                d3 = fmaf(zr[d + 3], E[j][d + 3], d3);
            }
            float dot  = (d0 + d1) + (d2 + d3);
            float dist = zsq - 2.0f * dot + Esq_s[j];
            if (dist < best) { best = dist; bidx = k0 + j; }
        }
        __syncthreads();
    }

    const float* e = cb + (size_t)bidx * DPC;
    __half* zp = zqh + (size_t)t * D_E + c * DPC;
    float cs = 0.0f;
#pragma unroll
    for (int q = 0; q < DPC / 4; q++) {
        float4 ev = *(const float4*)(e + q * 4);
        *(__half2*)(zp + 4 * q)     = __floats2half2_rn(ev.x, ev.y);
        *(__half2*)(zp + 4 * q + 2) = __floats2half2_rn(ev.z, ev.w);
        float dx = zr[4 * q + 0] - ev.x;
        float dy = zr[4 * q + 1] - ev.y;
        float dz = zr[4 * q + 2] - ev.z;
        float dw = zr[4 * q + 3] - ev.w;
        cs += dx * dx + dy * dy + dz * dz + dw * dw;
    }

    atomicAdd(&counts[c * NK + bidx], 1);
    out_idx[(size_t)t * NC + c] = (float)bidx;

    red[tid] = cs;
    __syncthreads();
    for (int s = VQ_TB / 2; s > 0; s >>= 1) {
        if (tid < s) red[tid] += red[tid + s];
        __syncthreads();
    }
    if (tid == 0) partials[blockIdx.y * gridDim.x + blockIdx.x] = red[0];
}

// ---------------------------------------------------------------------------
// Finalize scalars
// ---------------------------------------------------------------------------
__global__ void __launch_bounds__(256)
finalize_kernel(const float* __restrict__ partials, int npart,
                const int* __restrict__ counts, float* __restrict__ out_scalars)
{
    __shared__ float sm[256];
    const int tid = threadIdx.x;

    float v = (tid < npart) ? partials[tid] : 0.0f;
    sm[tid] = v;
    __syncthreads();
    for (int s = 128; s > 0; s >>= 1) {
        if (tid < s) sm[tid] += sm[tid + s];
        __syncthreads();
    }
    if (tid == 0) {
        float commitment = 0.25f * sm[0] / (float)(T_TOKENS * D_E);
        out_scalars[0] = commitment;
        out_scalars[1] = commitment;
    }

    float ent_acc = 0.0f;
    for (int c = 0; c < NC; c++) {
        float s = 0.0f;
        for (int k = tid; k < NK; k += 256) {
            float p = (float)counts[c * NK + k] * (1.0f / 8192.0f);
            s -= p * logf(p + 1e-10f);
        }
        __syncthreads();
        sm[tid] = s;
        __syncthreads();
        for (int st = 128; st > 0; st >>= 1) {
            if (tid < st) sm[tid] += sm[tid + st];
            __syncthreads();
        }
        if (tid == 0) ent_acc += sm[0];
        __syncthreads();
    }
    if (tid == 0) out_scalars[2] = ent_acc * 0.25f;
}

// ---------------------------------------------------------------------------
// Host launcher. Inputs: x, W1, b1, W2, b2, codebooks, W3, b3, W4, b4
// ---------------------------------------------------------------------------
extern "C" void kernel_launch(void* const* d_in, const int* in_sizes, int n_in,
                              void* d_out, int out_size)
{
    const float* x   = (const float*)d_in[0];
    const float* W1  = (const float*)d_in[1];
    const float* b1  = (const float*)d_in[2];
    const float* W2  = (const float*)d_in[3];
    const float* b2  = (const float*)d_in[4];
    const float* cb  = (const float*)d_in[5];
    const float* W3  = (const float*)d_in[6];
    const float* b3  = (const float*)d_in[7];
    const float* W4  = (const float*)d_in[8];
    const float* b4  = (const float*)d_in[9];

    float* out = (float*)d_out;

    float *z, *esq, *part;
    __half *xH, *xL, *w1H, *w1L, *w2H, *w2L, *h1H, *h1L, *zqh, *w3h, *h3h, *w4h;
    int* counts;
    cudaGetSymbolAddress((void**)&xH,  g_x_hi);
    cudaGetSymbolAddress((void**)&xL,  g_x_lo);
    cudaGetSymbolAddress((void**)&w1H, g_w1_hi);
    cudaGetSymbolAddress((void**)&w1L, g_w1_lo);
    cudaGetSymbolAddress((void**)&w2H, g_w2_hi);
    cudaGetSymbolAddress((void**)&w2L, g_w2_lo);
    cudaGetSymbolAddress((void**)&h1H, g_h1_hi);
    cudaGetSymbolAddress((void**)&h1L, g_h1_lo);
    cudaGetSymbolAddress((void**)&z,   g_z);
    cudaGetSymbolAddress((void**)&zqh, g_zq_h);
    cudaGetSymbolAddress((void**)&w3h, g_w3_h);
    cudaGetSymbolAddress((void**)&h3h, g_h3_h);
    cudaGetSymbolAddress((void**)&w4h, g_w4_h);
    cudaGetSymbolAddress((void**)&esq, g_esq);
    cudaGetSymbolAddress((void**)&part, g_part);
    cudaGetSymbolAddress((void**)&counts, g_counts);

    cudaFuncSetAttribute(splitf16_gemm_kernel,
                         cudaFuncAttributeMaxDynamicSharedMemorySize,
                         SMEM_SPLIT_BYTES);
    cudaFuncSetAttribute(h16_gemm_kernel,
                         cudaFuncAttributeMaxDynamicSharedMemorySize,
                         H16_SMEM_BYTES);

    // 0) conversions
    {
        int nx = T_TOKENS * D_IN;
        int n1 = D_IN * D_H1;
        int n2 = D_H1 * D_E;
        int n3 = D_E * D_H3;
        int n4 = D_H3 * D_OUT;
        f2h_split_kernel<<<(nx / 4 + 255) / 256, 256>>>(x, xH, xL, nx);
        f2h_split_kernel<<<(n1 / 4 + 255) / 256, 256>>>(W1, w1H, w1L, n1);
        f2h_split_kernel<<<(n2 / 4 + 255) / 256, 256>>>(W2, w2H, w2L, n2);
        f2h_kernel<<<(n3 / 4 + 255) / 256, 256>>>(W3, w3h, n3);
        f2h_kernel<<<(n4 / 4 + 255) / 256, 256>>>(W4, w4h, n4);
    }

    // 1) h1 = gelu(x @ W1 + b1)   split-fp16 3-term -> split-fp16 h1
    splitf16_gemm_kernel<<<dim3(D_H1 / 128, T_TOKENS / 128), 256,
                           SMEM_SPLIT_BYTES>>>(
        xH, xL, w1H, w1L, b1, nullptr, h1H, h1L,
        T_TOKENS, D_H1, D_IN, 1);

    // 2) z = h1 @ W2 + b2         split-fp16 3-term -> fp32 z
    splitf16_gemm_kernel<<<dim3(D_E / 128, T_TOKENS / 128), 256,
                           SMEM_SPLIT_BYTES>>>(
        h1H, h1L, w2H, w2L, b2, z, nullptr, nullptr,
        T_TOKENS, D_E, D_H1, 0);

    // 3) code norms + zero counts
    esq_kernel<<<(NC * NK + 255) / 256, 256>>>(cb, esq);
    zero_counts_kernel<<<(NC * NK + 255) / 256, 256>>>(counts);

    // 4) VQ (fp32 argmin, fp16 z_q)
    vq_kernel<<<dim3(T_TOKENS / VQ_TB, NC), VQ_TB>>>(
        z, cb, esq, zqh, out + XVQ_ELEMS, part, counts);

    // 5) scalars
    finalize_kernel<<<1, 256>>>(part, (T_TOKENS / VQ_TB) * NC, counts,
                                out + XVQ_ELEMS + IDX_ELEMS);

    // 6) h3 = gelu(zq @ W3 + b3)  fp16 4-stage single-barrier pipeline
    h16_gemm_kernel<<<dim3(D_H3 / 128, T_TOKENS / 128), 256, H16_SMEM_BYTES>>>(
        zqh, w3h, b3, nullptr, h3h, T_TOKENS, D_H3, D_E, 1);

    // 7) x_vq = h3 @ W4 + b4 -> out  fp16 4-stage single-barrier pipeline
    h16_gemm_kernel<<<dim3(D_OUT / 128, T_TOKENS / 128), 256, H16_SMEM_BYTES>>>(
        h3h, w4h, b4, out, nullptr, T_TOKENS, D_OUT, D_H3, 0);
}